// round 2
// baseline (speedup 1.0000x reference)
#include <cuda_runtime.h>
#include <cstdint>

#define N_NODES 100000
#define N_EDGES 1600000
#define DIM     128
#define T_NODES 4096
#define P_PAIRS 131072
#define HP      256
#define DOUT    128
#define ZDIM    64

// ---------------- scratch (static device globals; no allocation) ----------------
__device__ int   g_cnt[N_NODES];
__device__ int   g_rowptr[N_NODES + 1];
__device__ int   g_cursor[N_NODES];
__device__ int   g_col[N_EDGES];
__device__ float g_invdeg[N_NODES];
__device__ float g_pe[N_NODES * 4];
__device__ float g_zb[HP];
__device__ float g_buf1[(size_t)N_NODES * DIM];
__device__ float g_buf2[(size_t)N_NODES * DIM];
__device__ float g_hidden[(size_t)P_PAIRS * HP];

// ---------------- CSR build ----------------
__global__ void k_zero_cnt() {
    int i = blockIdx.x * blockDim.x + threadIdx.x;
    if (i < N_NODES) g_cnt[i] = 0;
}

__global__ void k_count(const int* __restrict__ dst) {
    int e = blockIdx.x * blockDim.x + threadIdx.x;
    if (e < N_EDGES) atomicAdd(&g_cnt[dst[e]], 1);
}

// single-block scan over N+1 entries
__global__ void k_scan() {
    __shared__ int sums[1024];
    const int CH = (N_NODES + 1024) / 1024;  // 98 -> 98*1024 = 100352 >= N+1
    int t = threadIdx.x;
    int base = t * CH;
    int s = 0;
    for (int i = 0; i < CH; i++) {
        int idx = base + i;
        if (idx < N_NODES) s += g_cnt[idx];
    }
    sums[t] = s;
    __syncthreads();
    for (int off = 1; off < 1024; off <<= 1) {
        int v = (t >= off) ? sums[t - off] : 0;
        __syncthreads();
        sums[t] += v;
        __syncthreads();
    }
    int run = sums[t] - s;  // exclusive prefix
    for (int i = 0; i < CH; i++) {
        int idx = base + i;
        if (idx <= N_NODES) g_rowptr[idx] = run;
        if (idx < N_NODES) run += g_cnt[idx];
    }
}

__global__ void k_prep() {
    int i = blockIdx.x * blockDim.x + threadIdx.x;
    if (i < N_NODES) {
        g_cursor[i] = g_rowptr[i];
        int c = g_cnt[i];
        g_invdeg[i] = 1.0f / (float)(c > 0 ? c : 1);
    }
}

__global__ void k_fill(const int* __restrict__ src, const int* __restrict__ dst) {
    int e = blockIdx.x * blockDim.x + threadIdx.x;
    if (e < N_EDGES) {
        int pos = atomicAdd(&g_cursor[dst[e]], 1);
        g_col[pos] = src[e];
    }
}

// ---------------- tiny precomputes ----------------
// pe = pos_enc @ Wpe.T  (Wpe is 4x4 row-major)
__global__ void k_pe(const float* __restrict__ pos_enc, const float* __restrict__ Wpe) {
    int n = blockIdx.x * blockDim.x + threadIdx.x;
    if (n >= N_NODES) return;
    float4 p = *(const float4*)&pos_enc[n * 4];
#pragma unroll
    for (int i = 0; i < 4; i++) {
        g_pe[n * 4 + i] = p.x * Wpe[i * 4 + 0] + p.y * Wpe[i * 4 + 1] +
                          p.z * Wpe[i * 4 + 2] + p.w * Wpe[i * 4 + 3];
    }
}

// zb[j] = bp1[j] + sum_i z[i] * Wp1[128+i][j]
__global__ void k_zb(const float* __restrict__ z, const float* __restrict__ Wp1,
                     const float* __restrict__ bp1) {
    int j = threadIdx.x;
    float acc = bp1[j];
    for (int i = 0; i < ZDIM; i++) acc = fmaf(z[i], Wp1[(128 + i) * HP + j], acc);
    g_zb[j] = acc;
}

// ---------------- SGEMM: C[M,128] = A[M,128] @ B[128,128] ----------------
__global__ void k_gemm128(const float* __restrict__ A, const float* __restrict__ B,
                          float* __restrict__ C, int M) {
    __shared__ float As[64][32];
    __shared__ float Bs[32][128];
    int m0 = blockIdx.x * 64;
    int tid = threadIdx.x;            // 256 threads
    int cg = tid & 31, rg = tid >> 5; // 32 col-groups x 8 row-groups
    float acc[8][4];
#pragma unroll
    for (int r = 0; r < 8; r++)
        acc[r][0] = acc[r][1] = acc[r][2] = acc[r][3] = 0.f;

    int lr = tid >> 3, lk = (tid & 7) << 2;   // A-load mapping
    int bkr = tid >> 5, bcq = (tid & 31) << 2; // B-load mapping

    for (int kc = 0; kc < 128; kc += 32) {
#pragma unroll
        for (int i = 0; i < 2; i++) {
            int row = m0 + lr + i * 32;
            float4 v = make_float4(0.f, 0.f, 0.f, 0.f);
            if (row < M) v = *(const float4*)&A[(size_t)row * 128 + kc + lk];
            *(float4*)&As[lr + i * 32][lk] = v;
        }
#pragma unroll
        for (int i = 0; i < 4; i++) {
            *(float4*)&Bs[bkr + i * 8][bcq] =
                *(const float4*)&B[(size_t)(kc + bkr + i * 8) * 128 + bcq];
        }
        __syncthreads();
#pragma unroll
        for (int k = 0; k < 32; k++) {
            float4 b = *(const float4*)&Bs[k][cg << 2];
#pragma unroll
            for (int r = 0; r < 8; r++) {
                float a = As[(rg << 3) + r][k];
                acc[r][0] = fmaf(a, b.x, acc[r][0]);
                acc[r][1] = fmaf(a, b.y, acc[r][1]);
                acc[r][2] = fmaf(a, b.z, acc[r][2]);
                acc[r][3] = fmaf(a, b.w, acc[r][3]);
            }
        }
        __syncthreads();
    }
#pragma unroll
    for (int r = 0; r < 8; r++) {
        int row = m0 + (rg << 3) + r;
        if (row < M)
            *(float4*)&C[(size_t)row * 128 + (cg << 2)] =
                make_float4(acc[r][0], acc[r][1], acc[r][2], acc[r][3]);
    }
}

// ---------------- CSR gather-aggregation ----------------
__global__ void k_agg(const float* __restrict__ in, float* __restrict__ out, int relu) {
    int n = blockIdx.x;
    int f = threadIdx.x;  // 128
    int s = g_rowptr[n], e = g_rowptr[n + 1];
    float a0 = 0.f, a1 = 0.f;
    int i = s;
    for (; i + 1 < e; i += 2) {
        a0 += in[(size_t)g_col[i] * 128 + f];
        a1 += in[(size_t)g_col[i + 1] * 128 + f];
    }
    if (i < e) a0 += in[(size_t)g_col[i] * 128 + f];
    float acc = (a0 + a1) * g_invdeg[n];
    if (relu) acc = fmaxf(acc, 0.f);
    out[(size_t)n * 128 + f] = acc;
}

// aggregate only for target nodes; write straight into output's embedding section
__global__ void k_agg_target(const float* __restrict__ in, const int* __restrict__ tgt,
                             float* __restrict__ out) {
    int b = blockIdx.x;
    int f = threadIdx.x;
    int n = tgt[b];
    int s = g_rowptr[n], e = g_rowptr[n + 1];
    float a0 = 0.f, a1 = 0.f;
    int i = s;
    for (; i + 1 < e; i += 2) {
        a0 += in[(size_t)g_col[i] * 128 + f];
        a1 += in[(size_t)g_col[i + 1] * 128 + f];
    }
    if (i < e) a0 += in[(size_t)g_col[i] * 128 + f];
    out[(size_t)b * 128 + f] = (a0 + a1) * g_invdeg[n];
}

// ---------------- predictor stage 1: hidden = relu(feat @ Wp1 + zb) ----------------
// feat(effective) = [ctx[pair_s] (128) | pe[pair_s] (4) | pe[tgt[pair_t]] (4)], K=136
__global__ void k_pred1(const float* __restrict__ ctx, const int* __restrict__ pair_s,
                        const int* __restrict__ pair_t, const int* __restrict__ tgt,
                        const float* __restrict__ mask, const float* __restrict__ Wp1) {
    int r0 = blockIdx.x * 16;
    int tid = threadIdx.x;  // 256
    int any = __syncthreads_or(tid < 16 && mask[r0 + tid] != 0.f);
    if (!any) return;  // stage 2 will zero-fill these rows

    __shared__ float feats[16][136];
#pragma unroll
    for (int i = 0; i < 2; i++) {
        int idx = tid + i * 256;
        int r = idx >> 5, q = (idx & 31) << 2;
        int sN = pair_s[r0 + r];
        *(float4*)&feats[r][q] = *(const float4*)&ctx[(size_t)sN * 128 + q];
    }
    if (tid < 16) {
        int r = tid;
        int sN = pair_s[r0 + r];
        int tN = tgt[pair_t[r0 + r]];
        *(float4*)&feats[r][128] = *(const float4*)&g_pe[sN * 4];
        *(float4*)&feats[r][132] = *(const float4*)&g_pe[tN * 4];
    }
    __syncthreads();

    int j = tid;  // hidden column
    float acc[16];
    float zbj = g_zb[j];
#pragma unroll
    for (int r = 0; r < 16; r++) acc[r] = zbj;

    for (int k4 = 0; k4 < 136; k4 += 4) {
        // Wp1 rows: 0..127 ctx, 192..195 pe_s, 196..199 pe_t (z-rows folded into zb)
        int wrow = (k4 < 128) ? k4 : (k4 == 128 ? 192 : 196);
        float w0 = Wp1[(wrow + 0) * HP + j];
        float w1 = Wp1[(wrow + 1) * HP + j];
        float w2 = Wp1[(wrow + 2) * HP + j];
        float w3 = Wp1[(wrow + 3) * HP + j];
#pragma unroll
        for (int r = 0; r < 16; r++) {
            float4 f = *(const float4*)&feats[r][k4];
            acc[r] = fmaf(f.x, w0, acc[r]);
            acc[r] = fmaf(f.y, w1, acc[r]);
            acc[r] = fmaf(f.z, w2, acc[r]);
            acc[r] = fmaf(f.w, w3, acc[r]);
        }
    }
#pragma unroll
    for (int r = 0; r < 16; r++)
        g_hidden[(size_t)(r0 + r) * HP + j] = fmaxf(acc[r], 0.f);
}

// ---------------- predictor stage 2: pred = (hidden @ Wp2 + bp2) * mask ----------------
__global__ void k_pred2(const float* __restrict__ Wp2, const float* __restrict__ bp2,
                        const float* __restrict__ mask, float* __restrict__ out) {
    int r0 = blockIdx.x * 16;
    int tid = threadIdx.x;  // 128
    __shared__ float ms[16];
    if (tid < 16) ms[tid] = mask[r0 + tid];
    int any = __syncthreads_or(tid < 16 && mask[r0 + tid] != 0.f);
    if (!any) {
#pragma unroll
        for (int r = 0; r < 16; r++) out[(size_t)(r0 + r) * 128 + tid] = 0.f;
        return;
    }
    __shared__ float hs[16][256];
#pragma unroll
    for (int i = 0; i < 8; i++) {
        int idx = tid + i * 128;
        int r = idx >> 6, q = (idx & 63) << 2;
        *(float4*)&hs[r][q] = *(const float4*)&g_hidden[(size_t)(r0 + r) * HP + q];
    }
    __syncthreads();

    int c = tid;
    float acc[16];
    float b = bp2[c];
#pragma unroll
    for (int r = 0; r < 16; r++) acc[r] = b;

    for (int k4 = 0; k4 < 256; k4 += 4) {
        float w0 = Wp2[(k4 + 0) * 128 + c];
        float w1 = Wp2[(k4 + 1) * 128 + c];
        float w2 = Wp2[(k4 + 2) * 128 + c];
        float w3 = Wp2[(k4 + 3) * 128 + c];
#pragma unroll
        for (int r = 0; r < 16; r++) {
            float4 h = *(const float4*)&hs[r][k4];
            acc[r] = fmaf(h.x, w0, acc[r]);
            acc[r] = fmaf(h.y, w1, acc[r]);
            acc[r] = fmaf(h.z, w2, acc[r]);
            acc[r] = fmaf(h.w, w3, acc[r]);
        }
    }
#pragma unroll
    for (int r = 0; r < 16; r++) out[(size_t)(r0 + r) * 128 + c] = acc[r] * ms[r];
}

// ---------------- launch ----------------
extern "C" void kernel_launch(void* const* d_in, const int* in_sizes, int n_in,
                              void* d_out, int out_size) {
    const float* x            = (const float*)d_in[0];
    const float* masked_x     = (const float*)d_in[1];
    const float* pos_enc      = (const float*)d_in[2];
    const int*   edge_src     = (const int*)d_in[3];
    const int*   edge_dst     = (const int*)d_in[4];
    const int*   target_nodes = (const int*)d_in[5];
    const int*   pair_t       = (const int*)d_in[6];
    const int*   pair_s       = (const int*)d_in[7];
    const float* pair_mask    = (const float*)d_in[8];
    const float* W1t          = (const float*)d_in[9];
    const float* W2t          = (const float*)d_in[10];
    const float* W1c          = (const float*)d_in[11];
    const float* W2c          = (const float*)d_in[12];
    const float* Wpe          = (const float*)d_in[13];
    const float* z            = (const float*)d_in[14];
    const float* Wp1          = (const float*)d_in[15];
    const float* bp1          = (const float*)d_in[16];
    const float* Wp2          = (const float*)d_in[17];
    const float* bp2          = (const float*)d_in[18];
    float* out = (float*)d_out;

    float *buf1, *buf2;
    cudaGetSymbolAddress((void**)&buf1, g_buf1);
    cudaGetSymbolAddress((void**)&buf2, g_buf2);

    const int TPB = 256;
    int gridN = (N_NODES + TPB - 1) / TPB;
    int gridE = (N_EDGES + TPB - 1) / TPB;
    int gridM = (N_NODES + 63) / 64;

    // CSR build (per launch; graph-capturable, deterministic work)
    k_zero_cnt<<<gridN, TPB>>>();
    k_count<<<gridE, TPB>>>(edge_dst);
    k_scan<<<1, 1024>>>();
    k_prep<<<gridN, TPB>>>();
    k_fill<<<gridE, TPB>>>(edge_src, edge_dst);

    // tiny precomputes
    k_pe<<<gridN, TPB>>>(pos_enc, Wpe);
    k_zb<<<1, HP>>>(z, Wp1, bp1);

    // target GCN (second agg only at target nodes, written straight to output)
    k_gemm128<<<gridM, 256>>>(x, W1t, buf1, N_NODES);
    k_agg<<<N_NODES, 128>>>(buf1, buf2, 1);
    k_gemm128<<<gridM, 256>>>(buf2, W2t, buf1, N_NODES);
    k_agg_target<<<T_NODES, 128>>>(buf1, target_nodes, out + (size_t)P_PAIRS * DOUT);

    // context GCN
    k_gemm128<<<gridM, 256>>>(masked_x, W1c, buf1, N_NODES);
    k_agg<<<N_NODES, 128>>>(buf1, buf2, 1);
    k_gemm128<<<gridM, 256>>>(buf2, W2c, buf1, N_NODES);
    k_agg<<<N_NODES, 128>>>(buf1, buf2, 0);  // ctx -> buf2

    // predictor MLP with mask-tile skipping
    k_pred1<<<P_PAIRS / 16, 256>>>(buf2, pair_s, pair_t, target_nodes, pair_mask, Wp1);
    k_pred2<<<P_PAIRS / 16, 128>>>(Wp2, bp2, pair_mask, out);
}

// round 3
// speedup vs baseline: 1.4155x; 1.4155x over previous
#include <cuda_runtime.h>
#include <cstdint>

#define N_NODES 100000
#define N_EDGES 1600000
#define DIM     128
#define T_NODES 4096
#define P_PAIRS 131072
#define HP      256
#define DOUT    128
#define ZDIM    64

// ---------------- scratch (static device globals; no allocation) ----------------
__device__ int   g_cnt[N_NODES];
__device__ int   g_rowptr[N_NODES + 1];
__device__ int   g_cursor[N_NODES];
__device__ int   g_col[N_EDGES];
__device__ float g_invdeg[N_NODES];
__device__ float g_pe[N_NODES * 4];
__device__ float g_zb[HP];
__device__ float g_wf[DIM * HP];                    // W2c @ Wp1[0:128]
__device__ float g_buf1[(size_t)N_NODES * DIM];
__device__ float g_buf2[(size_t)N_NODES * DIM];
__device__ float g_tbuf[(size_t)T_NODES * DIM];
__device__ float g_hidden[(size_t)P_PAIRS * HP];

// ---------------- CSR build ----------------
__global__ void k_zero_cnt() {
    int i = blockIdx.x * blockDim.x + threadIdx.x;
    if (i < N_NODES) g_cnt[i] = 0;
}

__global__ void k_count(const int* __restrict__ dst) {
    int e = blockIdx.x * blockDim.x + threadIdx.x;
    if (e < N_EDGES) atomicAdd(&g_cnt[dst[e]], 1);
}

__global__ void k_scan() {
    __shared__ int sums[1024];
    const int CH = (N_NODES + 1024) / 1024;
    int t = threadIdx.x;
    int base = t * CH;
    int s = 0;
    for (int i = 0; i < CH; i++) {
        int idx = base + i;
        if (idx < N_NODES) s += g_cnt[idx];
    }
    sums[t] = s;
    __syncthreads();
    for (int off = 1; off < 1024; off <<= 1) {
        int v = (t >= off) ? sums[t - off] : 0;
        __syncthreads();
        sums[t] += v;
        __syncthreads();
    }
    int run = sums[t] - s;
    for (int i = 0; i < CH; i++) {
        int idx = base + i;
        if (idx <= N_NODES) g_rowptr[idx] = run;
        if (idx < N_NODES) run += g_cnt[idx];
    }
}

__global__ void k_prep() {
    int i = blockIdx.x * blockDim.x + threadIdx.x;
    if (i < N_NODES) {
        g_cursor[i] = g_rowptr[i];
        int c = g_cnt[i];
        g_invdeg[i] = 1.0f / (float)(c > 0 ? c : 1);
    }
}

__global__ void k_fill(const int* __restrict__ src, const int* __restrict__ dst) {
    int e = blockIdx.x * blockDim.x + threadIdx.x;
    if (e < N_EDGES) {
        int pos = atomicAdd(&g_cursor[dst[e]], 1);
        g_col[pos] = src[e];
    }
}

// ---------------- tiny precomputes ----------------
__global__ void k_pe(const float* __restrict__ pos_enc, const float* __restrict__ Wpe) {
    int n = blockIdx.x * blockDim.x + threadIdx.x;
    if (n >= N_NODES) return;
    float4 p = *(const float4*)&pos_enc[n * 4];
#pragma unroll
    for (int i = 0; i < 4; i++) {
        g_pe[n * 4 + i] = p.x * Wpe[i * 4 + 0] + p.y * Wpe[i * 4 + 1] +
                          p.z * Wpe[i * 4 + 2] + p.w * Wpe[i * 4 + 3];
    }
}

// zb[j] = bp1[j] + sum_i z[i] * Wp1[128+i][j]
__global__ void k_zb(const float* __restrict__ z, const float* __restrict__ Wp1,
                     const float* __restrict__ bp1) {
    int j = threadIdx.x;
    float acc = bp1[j];
    for (int i = 0; i < ZDIM; i++) acc = fmaf(z[i], Wp1[(128 + i) * HP + j], acc);
    g_zb[j] = acc;
}

// Wf[i][j] = sum_d W2c[i][d] * Wp1[d][j]  (fold 2nd ctx GEMM into predictor)
__global__ void k_wf(const float* __restrict__ W2c, const float* __restrict__ Wp1) {
    int i = blockIdx.x;
    int j = threadIdx.x;
    float acc = 0.f;
    for (int d = 0; d < DIM; d++) acc = fmaf(W2c[i * DIM + d], Wp1[d * HP + j], acc);
    g_wf[i * HP + j] = acc;
}

// ---------------- SGEMM: C[M,128] = (relu?)(A[M,128] @ B[128,128]) ----------------
__global__ void k_gemm128(const float* __restrict__ A, const float* __restrict__ B,
                          float* __restrict__ C, int M, int relu) {
    __shared__ float As[64][32];
    __shared__ float Bs[32][128];
    int m0 = blockIdx.x * 64;
    int tid = threadIdx.x;            // 256
    int cg = tid & 31, rg = tid >> 5;
    float acc[8][4];
#pragma unroll
    for (int r = 0; r < 8; r++)
        acc[r][0] = acc[r][1] = acc[r][2] = acc[r][3] = 0.f;

    int lr = tid >> 3, lk = (tid & 7) << 2;
    int bkr = tid >> 5, bcq = (tid & 31) << 2;

    for (int kc = 0; kc < 128; kc += 32) {
#pragma unroll
        for (int i = 0; i < 2; i++) {
            int row = m0 + lr + i * 32;
            float4 v = make_float4(0.f, 0.f, 0.f, 0.f);
            if (row < M) v = *(const float4*)&A[(size_t)row * 128 + kc + lk];
            *(float4*)&As[lr + i * 32][lk] = v;
        }
#pragma unroll
        for (int i = 0; i < 4; i++) {
            *(float4*)&Bs[bkr + i * 8][bcq] =
                *(const float4*)&B[(size_t)(kc + bkr + i * 8) * 128 + bcq];
        }
        __syncthreads();
#pragma unroll
        for (int k = 0; k < 32; k++) {
            float4 b = *(const float4*)&Bs[k][cg << 2];
#pragma unroll
            for (int r = 0; r < 8; r++) {
                float a = As[(rg << 3) + r][k];
                acc[r][0] = fmaf(a, b.x, acc[r][0]);
                acc[r][1] = fmaf(a, b.y, acc[r][1]);
                acc[r][2] = fmaf(a, b.z, acc[r][2]);
                acc[r][3] = fmaf(a, b.w, acc[r][3]);
            }
        }
        __syncthreads();
    }
#pragma unroll
    for (int r = 0; r < 8; r++) {
        int row = m0 + (rg << 3) + r;
        if (row < M) {
            float4 v = make_float4(acc[r][0], acc[r][1], acc[r][2], acc[r][3]);
            if (relu) {
                v.x = fmaxf(v.x, 0.f); v.y = fmaxf(v.y, 0.f);
                v.z = fmaxf(v.z, 0.f); v.w = fmaxf(v.w, 0.f);
            }
            *(float4*)&C[(size_t)row * 128 + (cg << 2)] = v;
        }
    }
}

// ---------------- CSR gather-aggregation: warp per node, float4 lanes ----------------
__device__ __forceinline__ void agg_node(const float* __restrict__ in, int n, int lane,
                                         float4& r) {
    int s = g_rowptr[n], e = g_rowptr[n + 1];
    float4 a0 = make_float4(0.f, 0.f, 0.f, 0.f), a1 = a0, a2 = a0, a3 = a0;
    int i = s;
    for (; i + 4 <= e; i += 4) {
        int c0 = g_col[i], c1 = g_col[i + 1], c2 = g_col[i + 2], c3 = g_col[i + 3];
        float4 v0 = *(const float4*)&in[(size_t)c0 * 128 + lane * 4];
        float4 v1 = *(const float4*)&in[(size_t)c1 * 128 + lane * 4];
        float4 v2 = *(const float4*)&in[(size_t)c2 * 128 + lane * 4];
        float4 v3 = *(const float4*)&in[(size_t)c3 * 128 + lane * 4];
        a0.x += v0.x; a0.y += v0.y; a0.z += v0.z; a0.w += v0.w;
        a1.x += v1.x; a1.y += v1.y; a1.z += v1.z; a1.w += v1.w;
        a2.x += v2.x; a2.y += v2.y; a2.z += v2.z; a2.w += v2.w;
        a3.x += v3.x; a3.y += v3.y; a3.z += v3.z; a3.w += v3.w;
    }
    for (; i < e; i++) {
        int c = g_col[i];
        float4 v = *(const float4*)&in[(size_t)c * 128 + lane * 4];
        a0.x += v.x; a0.y += v.y; a0.z += v.z; a0.w += v.w;
    }
    float inv = g_invdeg[n];
    r.x = (a0.x + a1.x + a2.x + a3.x) * inv;
    r.y = (a0.y + a1.y + a2.y + a3.y) * inv;
    r.z = (a0.z + a1.z + a2.z + a3.z) * inv;
    r.w = (a0.w + a1.w + a2.w + a3.w) * inv;
}

__global__ void k_agg(const float* __restrict__ in, float* __restrict__ out) {
    int n = blockIdx.x * 8 + (threadIdx.x >> 5);
    if (n >= N_NODES) return;
    int lane = threadIdx.x & 31;
    float4 r;
    agg_node(in, n, lane, r);
    *(float4*)&out[(size_t)n * 128 + lane * 4] = r;
}

__global__ void k_agg_target(const float* __restrict__ in, const int* __restrict__ tgt,
                             float* __restrict__ out) {
    int b = blockIdx.x * 8 + (threadIdx.x >> 5);
    if (b >= T_NODES) return;
    int lane = threadIdx.x & 31;
    int n = tgt[b];
    float4 r;
    agg_node(in, n, lane, r);
    *(float4*)&out[(size_t)b * 128 + lane * 4] = r;
}

// ---------------- predictor stage 1: hidden = relu(m[pair_s]@Wf + pe-part + zb) ----
// 64-row tile, 256 threads, 8x8 register blocking.
// K layout: 0..127 -> g_wf rows; 128..135 -> Wp1 rows 192..199 (pe_s, pe_t).
__global__ void k_pred1(const float* __restrict__ m, const int* __restrict__ pair_s,
                        const int* __restrict__ pair_t, const int* __restrict__ tgt,
                        const float* __restrict__ mask, const float* __restrict__ Wp1) {
    int r0 = blockIdx.x * 64;
    int tid = threadIdx.x;
    int any = __syncthreads_or(tid < 64 && mask[r0 + tid] != 0.f);
    if (!any) return;  // pred2 zero-fills these rows

    __shared__ float feats[64 * 140];  // stride 140 (float4-aligned, bank-safe)
    __shared__ float ws[8 * 256];

#pragma unroll
    for (int i = 0; i < 8; i++) {
        int idx = tid + i * 256;          // 0..2047 = 64 rows x 32 float4
        int r = idx >> 5, q = (idx & 31) << 2;
        int sN = pair_s[r0 + r];
        *(float4*)&feats[r * 140 + q] = *(const float4*)&m[(size_t)sN * 128 + q];
    }
    if (tid < 64) {
        int sN = pair_s[r0 + tid];
        int tN = tgt[pair_t[r0 + tid]];
        *(float4*)&feats[tid * 140 + 128] = *(const float4*)&g_pe[sN * 4];
        *(float4*)&feats[tid * 140 + 132] = *(const float4*)&g_pe[tN * 4];
    }

    int rg = tid >> 5, cg = tid & 31;  // rg uniform per warp -> broadcast a-loads
    float acc[8][8];
#pragma unroll
    for (int r = 0; r < 8; r++)
#pragma unroll
        for (int c = 0; c < 8; c++) acc[r][c] = 0.f;

    for (int ch = 0; ch < 17; ch++) {
        {
            int kk = tid >> 5, j = (tid & 31) << 3;
            const float* src = (ch < 16) ? &g_wf[(ch * 8 + kk) * 256 + j]
                                         : &Wp1[(192 + kk) * 256 + j];
            *(float4*)&ws[kk * 256 + j]     = *(const float4*)src;
            *(float4*)&ws[kk * 256 + j + 4] = *(const float4*)(src + 4);
        }
        __syncthreads();
#pragma unroll
        for (int kk = 0; kk < 8; kk++) {
            int k = ch * 8 + kk;
            float a[8], b[8];
#pragma unroll
            for (int r = 0; r < 8; r++) a[r] = feats[(rg * 8 + r) * 140 + k];
#pragma unroll
            for (int c = 0; c < 8; c++) b[c] = ws[kk * 256 + cg + 32 * c];
#pragma unroll
            for (int r = 0; r < 8; r++)
#pragma unroll
                for (int c = 0; c < 8; c++) acc[r][c] = fmaf(a[r], b[c], acc[r][c]);
        }
        __syncthreads();
    }

#pragma unroll
    for (int c = 0; c < 8; c++) {
        float zbv = g_zb[cg + 32 * c];
#pragma unroll
        for (int r = 0; r < 8; r++) {
            int row = r0 + rg * 8 + r;
            g_hidden[(size_t)row * 256 + cg + 32 * c] = fmaxf(acc[r][c] + zbv, 0.f);
        }
    }
}

// ---------------- predictor stage 2: pred = (hidden @ Wp2 + bp2) * mask --------------
// 64-row tile, 256 threads, 8x4 register blocking, K=256 in chunks of 16.
__global__ void k_pred2(const float* __restrict__ Wp2, const float* __restrict__ bp2,
                        const float* __restrict__ mask, float* __restrict__ out) {
    int r0 = blockIdx.x * 64;
    int tid = threadIdx.x;
    __shared__ float ms[64];
    if (tid < 64) ms[tid] = mask[r0 + tid];
    int any = __syncthreads_or(tid < 64 && mask[r0 + tid] != 0.f);
    if (!any) {
        float4 zero = make_float4(0.f, 0.f, 0.f, 0.f);
#pragma unroll
        for (int i = 0; i < 8; i++) {
            int idx = tid + i * 256;
            *(float4*)&out[(size_t)r0 * 128 + idx * 4] = zero;
        }
        return;
    }

    __shared__ float As[64 * 17];      // hidden chunk, transposable-safe pad
    __shared__ float ws2[16 * 128];

    int rg = tid >> 5, cg = tid & 31;
    float acc[8][4];
#pragma unroll
    for (int r = 0; r < 8; r++)
#pragma unroll
        for (int c = 0; c < 4; c++) acc[r][c] = 0.f;

    for (int ch = 0; ch < 16; ch++) {
        {
            int r = tid >> 2, kq = (tid & 3) << 2;
            float4 v = *(const float4*)&g_hidden[(size_t)(r0 + r) * 256 + ch * 16 + kq];
            As[r * 17 + kq]     = v.x;
            As[r * 17 + kq + 1] = v.y;
            As[r * 17 + kq + 2] = v.z;
            As[r * 17 + kq + 3] = v.w;
        }
#pragma unroll
        for (int h = 0; h < 2; h++) {
            int kk = (tid >> 5) + h * 8;
            int j = tid & 31;
#pragma unroll
            for (int q = 0; q < 4; q++)
                ws2[kk * 128 + j + 32 * q] = Wp2[(size_t)(ch * 16 + kk) * 128 + j + 32 * q];
        }
        __syncthreads();
#pragma unroll
        for (int kk = 0; kk < 16; kk++) {
            float a[8], b[4];
#pragma unroll
            for (int r = 0; r < 8; r++) a[r] = As[(rg * 8 + r) * 17 + kk];
#pragma unroll
            for (int c = 0; c < 4; c++) b[c] = ws2[kk * 128 + cg + 32 * c];
#pragma unroll
            for (int r = 0; r < 8; r++)
#pragma unroll
                for (int c = 0; c < 4; c++) acc[r][c] = fmaf(a[r], b[c], acc[r][c]);
        }
        __syncthreads();
    }

#pragma unroll
    for (int c = 0; c < 4; c++) {
        float bb = bp2[cg + 32 * c];
#pragma unroll
        for (int r = 0; r < 8; r++) {
            int lr = rg * 8 + r;
            out[(size_t)(r0 + lr) * 128 + cg + 32 * c] = (acc[r][c] + bb) * ms[lr];
        }
    }
}

// ---------------- launch ----------------
extern "C" void kernel_launch(void* const* d_in, const int* in_sizes, int n_in,
                              void* d_out, int out_size) {
    const float* x            = (const float*)d_in[0];
    const float* masked_x     = (const float*)d_in[1];
    const float* pos_enc      = (const float*)d_in[2];
    const int*   edge_src     = (const int*)d_in[3];
    const int*   edge_dst     = (const int*)d_in[4];
    const int*   target_nodes = (const int*)d_in[5];
    const int*   pair_t       = (const int*)d_in[6];
    const int*   pair_s       = (const int*)d_in[7];
    const float* pair_mask    = (const float*)d_in[8];
    const float* W1t          = (const float*)d_in[9];
    const float* W2t          = (const float*)d_in[10];
    const float* W1c          = (const float*)d_in[11];
    const float* W2c          = (const float*)d_in[12];
    const float* Wpe          = (const float*)d_in[13];
    const float* z            = (const float*)d_in[14];
    const float* Wp1          = (const float*)d_in[15];
    const float* bp1          = (const float*)d_in[16];
    const float* Wp2          = (const float*)d_in[17];
    const float* bp2          = (const float*)d_in[18];
    float* out = (float*)d_out;

    float *buf1, *buf2, *tbuf;
    cudaGetSymbolAddress((void**)&buf1, g_buf1);
    cudaGetSymbolAddress((void**)&buf2, g_buf2);
    cudaGetSymbolAddress((void**)&tbuf, g_tbuf);

    const int TPB = 256;
    int gridN = (N_NODES + TPB - 1) / TPB;
    int gridE = (N_EDGES + TPB - 1) / TPB;
    int gridM = (N_NODES + 63) / 64;
    int gridA = (N_NODES + 7) / 8;     // warp-per-node aggs

    // CSR build
    k_zero_cnt<<<gridN, TPB>>>();
    k_count<<<gridE, TPB>>>(edge_dst);
    k_scan<<<1, 1024>>>();
    k_prep<<<gridN, TPB>>>();
    k_fill<<<gridE, TPB>>>(edge_src, edge_dst);

    // tiny precomputes
    k_pe<<<gridN, TPB>>>(pos_enc, Wpe);
    k_zb<<<1, HP>>>(z, Wp1, bp1);
    k_wf<<<DIM, HP>>>(W2c, Wp1);

    // target GCN: agg -> GEMM(relu) -> target-agg -> tiny GEMM straight to out
    k_agg<<<gridA, 256>>>(x, buf1);
    k_gemm128<<<gridM, 256>>>(buf1, W1t, buf2, N_NODES, 1);
    k_agg_target<<<(T_NODES + 7) / 8, 256>>>(buf2, target_nodes, tbuf);
    k_gemm128<<<(T_NODES + 63) / 64, 256>>>(tbuf, W2t, out + (size_t)P_PAIRS * DOUT,
                                            T_NODES, 0);

    // context GCN: agg -> GEMM(relu) -> agg  (2nd GEMM folded into Wf)
    k_agg<<<gridA, 256>>>(masked_x, buf1);
    k_gemm128<<<gridM, 256>>>(buf1, W1c, buf2, N_NODES, 1);
    k_agg<<<gridA, 256>>>(buf2, buf1);          // m = agg(h_c)

    // predictor MLP (64-row tiles, mask-tile skipping)
    k_pred1<<<P_PAIRS / 64, 256>>>(buf1, pair_s, pair_t, target_nodes, pair_mask, Wp1);
    k_pred2<<<P_PAIRS / 64, 256>>>(Wp2, bp2, pair_mask, out);
}